// round 11
// baseline (speedup 1.0000x reference)
#include <cuda_runtime.h>
#include <cuda_fp16.h>

static constexpr int N_NODES = 100000;
static constexpr int F_IN    = 128;
static constexpr int F_OUT   = 64;
static constexpr int N_EDGES = 1600000;
static constexpr int CAP     = 64;     // P(Poisson(16) > 64) ~ 1e-19 per node

// Scratch (static device arrays: no allocation).
// g_bucket slots >= deg(dst) are never written by ANY run (fill writes exactly
// deg records per dst per replay; array is zero-init) -> they hold src=0,
// w=+0.0f and contribute exactly 0 in accum. No tail predication needed.
__device__ __half             g_support[(size_t)N_NODES * F_OUT];   // 12.8 MB
__device__ int                g_cnt[N_NODES];                       // 0.4 MB
__device__ unsigned long long g_bucket[(size_t)N_NODES * CAP];      // 51.2 MB
__device__ int                g_idx_is_64;

// ---------------------------------------------------------------------------
// Prep: zero counters + probe int64/int32 edge_index (R8-exact).
// ---------------------------------------------------------------------------
__global__ __launch_bounds__(256) void prep_kernel(const long long* __restrict__ ei) {
    const int i = blockIdx.x * 256 + threadIdx.x;
    if (i < N_NODES / 4)
        reinterpret_cast<int4*>(g_cnt)[i] = make_int4(0, 0, 0, 0);

    if (blockIdx.x == 0 && threadIdx.x == 0) {
        bool is64 = true;
        #pragma unroll
        for (int j = 1; j <= 8; j++) {
            long long v = ei[j];
            if (v < 0 || v >= (long long)N_NODES) { is64 = false; break; }
        }
        g_idx_is_64 = is64 ? 1 : 0;
    }
}

// ---------------------------------------------------------------------------
// GEMM via tensor cores (R8-exact): fp16 in, fp32 accumulate, HMMA m16n8k16.
// ---------------------------------------------------------------------------
__device__ __forceinline__ unsigned h2u(__half2 h) {
    return *reinterpret_cast<unsigned*>(&h);
}

__global__ __launch_bounds__(256) void gemm_kernel(const float* __restrict__ X,
                                                   const float* __restrict__ W) {
    __shared__ __half sA[128 * 128];   // offA(r,k) = r*128 + ((k/8 ^ (r&7))*8) + k%8
    __shared__ __half sB[128 * 64];    // offB(k,n) = k*64  + ((n/8 ^ (k&7))*8) + n%8

    const int tid = threadIdx.x;
    const long long row0 = (long long)blockIdx.x * 128;

    #pragma unroll
    for (int it = 0; it < 4; it++) {
        const int i  = tid + 256 * it;
        const int k  = i >> 3;
        const int nc = i & 7;
        const float4 v0 = reinterpret_cast<const float4*>(W)[k * 16 + nc * 2];
        const float4 v1 = reinterpret_cast<const float4*>(W)[k * 16 + nc * 2 + 1];
        uint4 u;
        u.x = h2u(__floats2half2_rn(v0.x, v0.y));
        u.y = h2u(__floats2half2_rn(v0.z, v0.w));
        u.z = h2u(__floats2half2_rn(v1.x, v1.y));
        u.w = h2u(__floats2half2_rn(v1.z, v1.w));
        const int off = k * 64 + ((nc ^ (k & 7)) << 3);
        *reinterpret_cast<uint4*>(&sB[off]) = u;
    }

    #pragma unroll
    for (int it = 0; it < 8; it++) {
        const int i  = tid + 256 * it;
        const int r  = i >> 4;
        const int kc = i & 15;
        long long gr = row0 + r;
        if (gr >= N_NODES) gr = N_NODES - 1;
        const float4* xp = reinterpret_cast<const float4*>(X) + gr * 32 + kc * 2;
        const float4 v0 = xp[0];
        const float4 v1 = xp[1];
        uint4 u;
        u.x = h2u(__floats2half2_rn(v0.x, v0.y));
        u.y = h2u(__floats2half2_rn(v0.z, v0.w));
        u.z = h2u(__floats2half2_rn(v1.x, v1.y));
        u.w = h2u(__floats2half2_rn(v1.z, v1.w));
        const int off = r * 128 + ((kc ^ (r & 7)) << 3);
        *reinterpret_cast<uint4*>(&sA[off]) = u;
    }
    __syncthreads();

    const int warp = tid >> 5;
    const int lane = tid & 31;
    const int r0w  = warp << 4;

    const unsigned aBase = (unsigned)__cvta_generic_to_shared(sA);
    const unsigned bBase = (unsigned)__cvta_generic_to_shared(sB);

    const int arow  = r0w + (lane & 15);
    const int akoff = (lane >> 4) << 3;
    const int sel        = lane >> 3;
    const int brow_local = ((sel & 1) << 3) + (lane & 7);
    const int bnt_half   = sel >> 1;

    float acc[8][4];
    #pragma unroll
    for (int t = 0; t < 8; t++)
        #pragma unroll
        for (int c = 0; c < 4; c++) acc[t][c] = 0.f;

    #pragma unroll
    for (int kc8 = 0; kc8 < 8; kc8++) {
        const int kc = kc8 * 16;

        unsigned a0, a1, a2, a3;
        {
            const int k   = kc + akoff;
            const int off = arow * 128 + (((k >> 3) ^ (arow & 7)) << 3);
            asm volatile("ldmatrix.sync.aligned.m8n8.x4.shared.b16 {%0,%1,%2,%3}, [%4];"
                         : "=r"(a0), "=r"(a1), "=r"(a2), "=r"(a3)
                         : "r"(aBase + off * 2));
        }

        unsigned b[8][2];
        #pragma unroll
        for (int p = 0; p < 4; p++) {
            const int nt   = 2 * p + bnt_half;
            const int krow = kc + brow_local;
            const int off  = krow * 64 + ((nt ^ (krow & 7)) << 3);
            asm volatile("ldmatrix.sync.aligned.m8n8.x4.trans.shared.b16 {%0,%1,%2,%3}, [%4];"
                         : "=r"(b[2 * p][0]), "=r"(b[2 * p][1]),
                           "=r"(b[2 * p + 1][0]), "=r"(b[2 * p + 1][1])
                         : "r"(bBase + off * 2));
        }

        #pragma unroll
        for (int t = 0; t < 8; t++) {
            asm volatile(
                "mma.sync.aligned.m16n8k16.row.col.f32.f16.f16.f32 "
                "{%0,%1,%2,%3}, {%4,%5,%6,%7}, {%8,%9}, {%0,%1,%2,%3};"
                : "+f"(acc[t][0]), "+f"(acc[t][1]), "+f"(acc[t][2]), "+f"(acc[t][3])
                : "r"(a0), "r"(a1), "r"(a2), "r"(a3), "r"(b[t][0]), "r"(b[t][1]));
        }
    }

    const int g  = lane >> 2;
    const int t4 = lane & 3;
    #pragma unroll
    for (int t = 0; t < 8; t++) {
        const int ncol = t * 8 + t4 * 2;
        const long long rA = row0 + r0w + g;
        if (rA < N_NODES) {
            const __half2 h = __floats2half2_rn(acc[t][0], acc[t][1]);
            *reinterpret_cast<__half2*>(&g_support[rA * 64 + ncol]) = h;
        }
        const long long rB = rA + 8;
        if (rB < N_NODES) {
            const __half2 h = __floats2half2_rn(acc[t][2], acc[t][3]);
            *reinterpret_cast<__half2*>(&g_support[rB * 64 + ncol]) = h;
        }
    }
}

// ---------------------------------------------------------------------------
// Fill: 4 edges per thread (R8-exact).
// ---------------------------------------------------------------------------
__global__ __launch_bounds__(256) void fill_kernel(const void* __restrict__ eiv,
                                                   const float* __restrict__ ew) {
    const int e0 = (blockIdx.x * 256 + threadIdx.x) * 4;
    if (e0 >= N_EDGES) return;   // N_EDGES % 4 == 0

    int dst[4], src[4];
    if (g_idx_is_64) {
        const longlong2* ei = (const longlong2*)eiv;
        longlong2 d0 = ei[e0 / 2], d1 = ei[e0 / 2 + 1];
        longlong2 s0 = ei[(N_EDGES + e0) / 2], s1 = ei[(N_EDGES + e0) / 2 + 1];
        dst[0] = (int)d0.x; dst[1] = (int)d0.y; dst[2] = (int)d1.x; dst[3] = (int)d1.y;
        src[0] = (int)s0.x; src[1] = (int)s0.y; src[2] = (int)s1.x; src[3] = (int)s1.y;
    } else {
        const int4* ei = (const int4*)eiv;
        int4 d = ei[e0 / 4];
        int4 s = ei[(N_EDGES + e0) / 4];
        dst[0] = d.x; dst[1] = d.y; dst[2] = d.z; dst[3] = d.w;
        src[0] = s.x; src[1] = s.y; src[2] = s.z; src[3] = s.w;
    }

    const float4 wv = reinterpret_cast<const float4*>(ew)[e0 / 4];
    const float w[4] = {wv.x, wv.y, wv.z, wv.w};

    int pos[4];
    #pragma unroll
    for (int j = 0; j < 4; j++)
        pos[j] = atomicAdd(&g_cnt[dst[j]], 1);

    #pragma unroll
    for (int j = 0; j < 4; j++) {
        if (pos[j] < CAP) {
            unsigned long long rec = (unsigned long long)(unsigned)src[j]
                                   | ((unsigned long long)__float_as_uint(w[j]) << 32);
            g_bucket[(size_t)dst[j] * CAP + pos[j]] = rec;
        }
    }
}

// ---------------------------------------------------------------------------
// Accumulate + fused ReLU: ONE WARP PER DST. Lane l owns cols {2l, 2l+1}
// (one half2 -> LDG.32 gather, a full row = 1 x 128B wavefront per edge).
// Trip count = ceil(own deg / 4): no inter-group divergence, <=3 edges of
// zero-weight tail (slots are permanently zero). 4 gathers in flight per trip.
// ---------------------------------------------------------------------------
__global__ __launch_bounds__(256) void accum_kernel(float* __restrict__ out) {
    const int gwarp = (blockIdx.x * 256 + threadIdx.x) >> 5;   // = dst
    const int lane  = threadIdx.x & 31;
    const int dst   = gwarp;                                   // grid sized exactly

    const int deg = min(g_cnt[dst], CAP);

    const ulonglong2* bkt2 = reinterpret_cast<const ulonglong2*>(
                                 &g_bucket[(size_t)dst * CAP]);
    const unsigned* supc = reinterpret_cast<const unsigned*>(g_support) + lane;

    unsigned long long acc = 0ull;   // packed f32x2 for cols {2*lane, 2*lane+1}

    const int nb = (deg + 3) >> 2;   // 4 edges per trip
    for (int it = 0; it < nb; it++) {
        const ulonglong2 rp0 = __ldg(&bkt2[2 * it]);       // records 4it, 4it+1
        const ulonglong2 rp1 = __ldg(&bkt2[2 * it + 1]);   // records 4it+2, 4it+3

        const unsigned long long recs[4] = {rp0.x, rp0.y, rp1.x, rp1.y};
        #pragma unroll
        for (int j = 0; j < 4; j++) {
            const int   src = (int)(unsigned)recs[j];
            const float w   = __uint_as_float((unsigned)(recs[j] >> 32));
            const unsigned u = __ldg(&supc[(long long)src * 32]);   // half2
            const float2 f = __half22float2(*reinterpret_cast<const __half2*>(&u));

            unsigned long long ws, sv;
            asm("mov.b64 %0, {%1, %1};" : "=l"(ws) : "f"(w));
            asm("mov.b64 %0, {%1, %2};" : "=l"(sv) : "f"(f.x), "f"(f.y));
            asm("fma.rn.f32x2 %0, %1, %2, %0;" : "+l"(acc) : "l"(ws), "l"(sv));
        }
    }

    float2 v;
    asm("mov.b64 {%0, %1}, %2;" : "=f"(v.x), "=f"(v.y) : "l"(acc));
    v.x = fmaxf(v.x, 0.f);
    v.y = fmaxf(v.y, 0.f);
    reinterpret_cast<float2*>(out)[(long long)dst * 32 + lane] = v;
}

extern "C" void kernel_launch(void* const* d_in, const int* in_sizes, int n_in,
                              void* d_out, int out_size) {
    const float* X  = (const float*)d_in[0];   // [100000, 128] f32
    const float* W  = (const float*)d_in[1];   // [128, 64]     f32
    const void*  EI = d_in[2];                 // [2, 1600000]  int64 or int32
    const float* EW = (const float*)d_in[3];   // [1600000]     f32
    float* out = (float*)d_out;                // [100000, 64]  f32

    prep_kernel<<<(N_NODES / 4 + 255) / 256, 256>>>((const long long*)EI);

    gemm_kernel<<<(N_NODES + 127) / 128, 256>>>(X, W);

    fill_kernel<<<(N_EDGES / 4 + 255) / 256, 256>>>(EI, EW);

    // one warp per dst: 100000 warps * 32 / 256 = 12500 blocks
    accum_kernel<<<(N_NODES * 32) / 256, 256>>>(out);
}

// round 12
// speedup vs baseline: 1.1216x; 1.1216x over previous
#include <cuda_runtime.h>
#include <cuda_fp16.h>

static constexpr int N_NODES = 100000;
static constexpr int F_IN    = 128;
static constexpr int F_OUT   = 64;
static constexpr int N_EDGES = 1600000;
static constexpr int CAP     = 64;     // P(Poisson(16) > 64) ~ 1e-19 per node

// Scratch (static device arrays: no allocation).
// g_bucket slots >= deg(dst) are never written by ANY run (fill writes exactly
// deg records per dst per replay; array is zero-init) -> they hold src=0,
// w=+0.0f and contribute exactly 0 in accum. No tail predication needed.
__device__ __half             g_support[(size_t)N_NODES * F_OUT];   // 12.8 MB
__device__ int                g_cnt[N_NODES];                       // 0.4 MB
__device__ unsigned long long g_bucket[(size_t)N_NODES * CAP];      // 51.2 MB
__device__ int                g_idx_is_64;

// ---------------------------------------------------------------------------
// Prep: zero counters + probe int64/int32 edge_index (R8-exact).
// ---------------------------------------------------------------------------
__global__ __launch_bounds__(256) void prep_kernel(const long long* __restrict__ ei) {
    const int i = blockIdx.x * 256 + threadIdx.x;
    if (i < N_NODES / 4)
        reinterpret_cast<int4*>(g_cnt)[i] = make_int4(0, 0, 0, 0);

    if (blockIdx.x == 0 && threadIdx.x == 0) {
        bool is64 = true;
        #pragma unroll
        for (int j = 1; j <= 8; j++) {
            long long v = ei[j];
            if (v < 0 || v >= (long long)N_NODES) { is64 = false; break; }
        }
        g_idx_is_64 = is64 ? 1 : 0;
    }
}

// ---------------------------------------------------------------------------
// GEMM via tensor cores (R8-exact): fp16 in, fp32 accumulate, HMMA m16n8k16.
// ---------------------------------------------------------------------------
__device__ __forceinline__ unsigned h2u(__half2 h) {
    return *reinterpret_cast<unsigned*>(&h);
}

__global__ __launch_bounds__(256) void gemm_kernel(const float* __restrict__ X,
                                                   const float* __restrict__ W) {
    __shared__ __half sA[128 * 128];   // offA(r,k) = r*128 + ((k/8 ^ (r&7))*8) + k%8
    __shared__ __half sB[128 * 64];    // offB(k,n) = k*64  + ((n/8 ^ (k&7))*8) + n%8

    const int tid = threadIdx.x;
    const long long row0 = (long long)blockIdx.x * 128;

    #pragma unroll
    for (int it = 0; it < 4; it++) {
        const int i  = tid + 256 * it;
        const int k  = i >> 3;
        const int nc = i & 7;
        const float4 v0 = reinterpret_cast<const float4*>(W)[k * 16 + nc * 2];
        const float4 v1 = reinterpret_cast<const float4*>(W)[k * 16 + nc * 2 + 1];
        uint4 u;
        u.x = h2u(__floats2half2_rn(v0.x, v0.y));
        u.y = h2u(__floats2half2_rn(v0.z, v0.w));
        u.z = h2u(__floats2half2_rn(v1.x, v1.y));
        u.w = h2u(__floats2half2_rn(v1.z, v1.w));
        const int off = k * 64 + ((nc ^ (k & 7)) << 3);
        *reinterpret_cast<uint4*>(&sB[off]) = u;
    }

    #pragma unroll
    for (int it = 0; it < 8; it++) {
        const int i  = tid + 256 * it;
        const int r  = i >> 4;
        const int kc = i & 15;
        long long gr = row0 + r;
        if (gr >= N_NODES) gr = N_NODES - 1;
        const float4* xp = reinterpret_cast<const float4*>(X) + gr * 32 + kc * 2;
        const float4 v0 = xp[0];
        const float4 v1 = xp[1];
        uint4 u;
        u.x = h2u(__floats2half2_rn(v0.x, v0.y));
        u.y = h2u(__floats2half2_rn(v0.z, v0.w));
        u.z = h2u(__floats2half2_rn(v1.x, v1.y));
        u.w = h2u(__floats2half2_rn(v1.z, v1.w));
        const int off = r * 128 + ((kc ^ (r & 7)) << 3);
        *reinterpret_cast<uint4*>(&sA[off]) = u;
    }
    __syncthreads();

    const int warp = tid >> 5;
    const int lane = tid & 31;
    const int r0w  = warp << 4;

    const unsigned aBase = (unsigned)__cvta_generic_to_shared(sA);
    const unsigned bBase = (unsigned)__cvta_generic_to_shared(sB);

    const int arow  = r0w + (lane & 15);
    const int akoff = (lane >> 4) << 3;
    const int sel        = lane >> 3;
    const int brow_local = ((sel & 1) << 3) + (lane & 7);
    const int bnt_half   = sel >> 1;

    float acc[8][4];
    #pragma unroll
    for (int t = 0; t < 8; t++)
        #pragma unroll
        for (int c = 0; c < 4; c++) acc[t][c] = 0.f;

    #pragma unroll
    for (int kc8 = 0; kc8 < 8; kc8++) {
        const int kc = kc8 * 16;

        unsigned a0, a1, a2, a3;
        {
            const int k   = kc + akoff;
            const int off = arow * 128 + (((k >> 3) ^ (arow & 7)) << 3);
            asm volatile("ldmatrix.sync.aligned.m8n8.x4.shared.b16 {%0,%1,%2,%3}, [%4];"
                         : "=r"(a0), "=r"(a1), "=r"(a2), "=r"(a3)
                         : "r"(aBase + off * 2));
        }

        unsigned b[8][2];
        #pragma unroll
        for (int p = 0; p < 4; p++) {
            const int nt   = 2 * p + bnt_half;
            const int krow = kc + brow_local;
            const int off  = krow * 64 + ((nt ^ (krow & 7)) << 3);
            asm volatile("ldmatrix.sync.aligned.m8n8.x4.trans.shared.b16 {%0,%1,%2,%3}, [%4];"
                         : "=r"(b[2 * p][0]), "=r"(b[2 * p][1]),
                           "=r"(b[2 * p + 1][0]), "=r"(b[2 * p + 1][1])
                         : "r"(bBase + off * 2));
        }

        #pragma unroll
        for (int t = 0; t < 8; t++) {
            asm volatile(
                "mma.sync.aligned.m16n8k16.row.col.f32.f16.f16.f32 "
                "{%0,%1,%2,%3}, {%4,%5,%6,%7}, {%8,%9}, {%0,%1,%2,%3};"
                : "+f"(acc[t][0]), "+f"(acc[t][1]), "+f"(acc[t][2]), "+f"(acc[t][3])
                : "r"(a0), "r"(a1), "r"(a2), "r"(a3), "r"(b[t][0]), "r"(b[t][1]));
        }
    }

    const int g  = lane >> 2;
    const int t4 = lane & 3;
    #pragma unroll
    for (int t = 0; t < 8; t++) {
        const int ncol = t * 8 + t4 * 2;
        const long long rA = row0 + r0w + g;
        if (rA < N_NODES) {
            const __half2 h = __floats2half2_rn(acc[t][0], acc[t][1]);
            *reinterpret_cast<__half2*>(&g_support[rA * 64 + ncol]) = h;
        }
        const long long rB = rA + 8;
        if (rB < N_NODES) {
            const __half2 h = __floats2half2_rn(acc[t][2], acc[t][3]);
            *reinterpret_cast<__half2*>(&g_support[rB * 64 + ncol]) = h;
        }
    }
}

// ---------------------------------------------------------------------------
// Fill: 4 edges per thread (R8-exact).
// ---------------------------------------------------------------------------
__global__ __launch_bounds__(256) void fill_kernel(const void* __restrict__ eiv,
                                                   const float* __restrict__ ew) {
    const int e0 = (blockIdx.x * 256 + threadIdx.x) * 4;
    if (e0 >= N_EDGES) return;   // N_EDGES % 4 == 0

    int dst[4], src[4];
    if (g_idx_is_64) {
        const longlong2* ei = (const longlong2*)eiv;
        longlong2 d0 = ei[e0 / 2], d1 = ei[e0 / 2 + 1];
        longlong2 s0 = ei[(N_EDGES + e0) / 2], s1 = ei[(N_EDGES + e0) / 2 + 1];
        dst[0] = (int)d0.x; dst[1] = (int)d0.y; dst[2] = (int)d1.x; dst[3] = (int)d1.y;
        src[0] = (int)s0.x; src[1] = (int)s0.y; src[2] = (int)s1.x; src[3] = (int)s1.y;
    } else {
        const int4* ei = (const int4*)eiv;
        int4 d = ei[e0 / 4];
        int4 s = ei[(N_EDGES + e0) / 4];
        dst[0] = d.x; dst[1] = d.y; dst[2] = d.z; dst[3] = d.w;
        src[0] = s.x; src[1] = s.y; src[2] = s.z; src[3] = s.w;
    }

    const float4 wv = reinterpret_cast<const float4*>(ew)[e0 / 4];
    const float w[4] = {wv.x, wv.y, wv.z, wv.w};

    int pos[4];
    #pragma unroll
    for (int j = 0; j < 4; j++)
        pos[j] = atomicAdd(&g_cnt[dst[j]], 1);

    #pragma unroll
    for (int j = 0; j < 4; j++) {
        if (pos[j] < CAP) {
            unsigned long long rec = (unsigned long long)(unsigned)src[j]
                                   | ((unsigned long long)__float_as_uint(w[j]) << 32);
            g_bucket[(size_t)dst[j] * CAP + pos[j]] = rec;
        }
    }
}

// ---------------------------------------------------------------------------
// Accumulate + fused ReLU: R10 layout (16 threads/dst, 4 cols/thread, no
// shuffles, no tail predication, packed f32x2 FMA) but 8-edge batches:
// waste drops 47% -> 26% (deg ~ Poisson(16)); gather MLP stays 8.
// ---------------------------------------------------------------------------
__global__ __launch_bounds__(256) void accum_kernel(float* __restrict__ out) {
    const int idx = blockIdx.x * 256 + threadIdx.x;
    const int dst = idx >> 4;
    const int cg  = idx & 15;

    const int deg = min(g_cnt[dst], CAP);

    const ulonglong2* bkt2 = reinterpret_cast<const ulonglong2*>(
                                 &g_bucket[(size_t)dst * CAP]);
    const uint2* supc = reinterpret_cast<const uint2*>(g_support) + cg;

    unsigned long long acc01 = 0ull, acc23 = 0ull;   // packed f32x2 accumulators

    for (int base = 0; base < deg; base += 8) {
        #pragma unroll
        for (int i2 = 0; i2 < 4; i2++) {
            const ulonglong2 rp = __ldg(&bkt2[(base >> 1) + i2]);   // 2 records

            #pragma unroll
            for (int h = 0; h < 2; h++) {
                const unsigned long long rec = h ? rp.y : rp.x;
                const int   src = (int)(unsigned)rec;
                const float w   = __uint_as_float((unsigned)(rec >> 32));
                const uint2 u = __ldg(&supc[(long long)src * 16]);
                const float2 f0 = __half22float2(*reinterpret_cast<const __half2*>(&u.x));
                const float2 f1 = __half22float2(*reinterpret_cast<const __half2*>(&u.y));

                unsigned long long ws, s01, s23;
                asm("mov.b64 %0, {%1, %1};" : "=l"(ws)  : "f"(w));
                asm("mov.b64 %0, {%1, %2};" : "=l"(s01) : "f"(f0.x), "f"(f0.y));
                asm("mov.b64 %0, {%1, %2};" : "=l"(s23) : "f"(f1.x), "f"(f1.y));
                asm("fma.rn.f32x2 %0, %1, %2, %0;" : "+l"(acc01) : "l"(ws), "l"(s01));
                asm("fma.rn.f32x2 %0, %1, %2, %0;" : "+l"(acc23) : "l"(ws), "l"(s23));
            }
        }
    }

    float4 v;
    asm("mov.b64 {%0, %1}, %2;" : "=f"(v.x), "=f"(v.y) : "l"(acc01));
    asm("mov.b64 {%0, %1}, %2;" : "=f"(v.z), "=f"(v.w) : "l"(acc23));
    v.x = fmaxf(v.x, 0.f);
    v.y = fmaxf(v.y, 0.f);
    v.z = fmaxf(v.z, 0.f);
    v.w = fmaxf(v.w, 0.f);
    reinterpret_cast<float4*>(out)[(long long)dst * 16 + cg] = v;
}

extern "C" void kernel_launch(void* const* d_in, const int* in_sizes, int n_in,
                              void* d_out, int out_size) {
    const float* X  = (const float*)d_in[0];   // [100000, 128] f32
    const float* W  = (const float*)d_in[1];   // [128, 64]     f32
    const void*  EI = d_in[2];                 // [2, 1600000]  int64 or int32
    const float* EW = (const float*)d_in[3];   // [1600000]     f32
    float* out = (float*)d_out;                // [100000, 64]  f32

    // Side stream + events: created once on the (uncaptured) correctness call,
    // reused by the capture call. Same launches issued on every call — the
    // work is identical each time; only infra handles are lazily built.
    static cudaStream_t s2  = nullptr;
    static cudaEvent_t  ev0 = nullptr, ev1 = nullptr;
    if (s2 == nullptr) {
        cudaStreamCreateWithFlags(&s2, cudaStreamNonBlocking);
        cudaEventCreateWithFlags(&ev0, cudaEventDisableTiming);
        cudaEventCreateWithFlags(&ev1, cudaEventDisableTiming);
    }

    // Fork: gemm (X,W -> support) runs on s2 concurrently with prep+fill
    // (EI,EW -> counters+buckets) on the main stream. Join before accum,
    // which consumes both.
    cudaEventRecord(ev0, 0);
    cudaStreamWaitEvent(s2, ev0, 0);
    gemm_kernel<<<(N_NODES + 127) / 128, 256, 0, s2>>>(X, W);
    cudaEventRecord(ev1, s2);

    prep_kernel<<<(N_NODES / 4 + 255) / 256, 256>>>((const long long*)EI);
    fill_kernel<<<(N_EDGES / 4 + 255) / 256, 256>>>(EI, EW);

    cudaStreamWaitEvent(0, ev1, 0);
    accum_kernel<<<(N_NODES * 16) / 256, 256>>>(out);
}